// round 14
// baseline (speedup 1.0000x reference)
#include <cuda_runtime.h>
#include <cuda_bf16.h>

typedef unsigned long long ull;
typedef unsigned int u32;

#define NN 50000
#define EE 800000
#define NTILE 6250
#define NEG_SLOPE 0.2f
#define LN_EPS 1e-5f

// ---------------- scratch ----------------
__device__ float g_xn[(size_t)NN * 128];
__device__ float g_xl[(size_t)NN * 128];
__device__ float g_xr[(size_t)NN * 128];
__device__ float g_ew[(size_t)EE * 8];
__device__ int g_src[EE], g_dst[EE];
__device__ int g_deg[NN], g_start[NN], g_cursor[NN], g_incl[NN];
__device__ int g_csr[EE];
__device__ int g_bsum[64];
__device__ int g_is64;
__device__ int g_tile;
// bf16 hi/lo weight images, padded rows [128][136] bf16 = 34816 B = 2176 uint4 each
__device__ uint4 g_Bth[2176], g_Btl[2176];          // W_e^T
__device__ uint4 g_Wth[4352], g_Wtl[4352];          // [Wl^T | Wr^T]

__device__ __forceinline__ u32 smem_u32(const void* p) {
    u32 a;
    asm("{ .reg .u64 t; cvta.to.shared.u64 t, %1; cvt.u32.u64 %0, t; }" : "=r"(a) : "l"(p));
    return a;
}

// ---------------- init: zero deg + dtype detect ----------------
__global__ void kdetect(const int* p) {
    int i = blockIdx.x * 256 + threadIdx.x;
    if (i < NN) g_deg[i] = 0;
    if (i == 0) {
        int s = 0;
        for (int j = 1; j < 256; j += 2) s |= p[j];
        g_is64 = (s == 0) ? 1 : 0;
        g_tile = 0;
    }
}
// convert + fused degree histogram
__global__ void kconvert(const void* ei) {
    int i = blockIdx.x * 256 + threadIdx.x;
    if (i >= EE) return;
    int s, d;
    if (g_is64) {
        const long long* p = (const long long*)ei;
        s = (int)p[i];
        d = (int)p[EE + i];
    } else {
        const int* p = (const int*)ei;
        s = p[i];
        d = p[EE + i];
    }
    g_src[i] = s;
    g_dst[i] = d;
    atomicAdd(&g_deg[d], 1);
}

// ---------------- LayerNorm: one warp per node ----------------
__global__ void kln(const float* __restrict__ x, const float* __restrict__ gamma,
                    const float* __restrict__ beta) {
    int w = threadIdx.x >> 5, lane = threadIdx.x & 31;
    int n = blockIdx.x * 8 + w;
    if (n >= NN) return;
    float4 v = *(const float4*)(x + (size_t)n * 128 + lane * 4);
    float s = v.x + v.y + v.z + v.w;
    float sq = v.x * v.x + v.y * v.y + v.z * v.z + v.w * v.w;
#pragma unroll
    for (int o = 16; o > 0; o >>= 1) {
        s += __shfl_xor_sync(0xffffffffu, s, o);
        sq += __shfl_xor_sync(0xffffffffu, sq, o);
    }
    float mean = s * (1.f / 128.f);
    float var = sq * (1.f / 128.f) - mean * mean;
    float inv = rsqrtf(var + LN_EPS);
    float4 g = *(const float4*)(gamma + lane * 4);
    float4 b = *(const float4*)(beta + lane * 4);
    float4 o;
    o.x = (v.x - mean) * inv * g.x + b.x;
    o.y = (v.y - mean) * inv * g.y + b.y;
    o.z = (v.z - mean) * inv * g.z + b.z;
    o.w = (v.w - mean) * inv * g.w + b.w;
    *(float4*)(g_xn + (size_t)n * 128 + lane * 4) = o;
}

// ---------------- weight prep: transpose + bf16 hi/lo split ----------------
__global__ void kprepB(const float* __restrict__ We) {
    int i = blockIdx.x * 256 + threadIdx.x;   // 16384
    int k = i >> 7, n = i & 127;
    float v = We[i];
    __nv_bfloat16 h = __float2bfloat16(v);
    __nv_bfloat16 l = __float2bfloat16(v - __bfloat162float(h));
    ((__nv_bfloat16*)g_Bth)[n * 136 + k] = h;
    ((__nv_bfloat16*)g_Btl)[n * 136 + k] = l;
}
__global__ void kprepW(const float* __restrict__ Wl, const float* __restrict__ Wr) {
    int i = blockIdx.x * 256 + threadIdx.x;   // 32768
    int sel = i >> 14, j = i & 16383;
    int k = j >> 7, n = j & 127;
    float v = sel ? Wr[j] : Wl[j];
    __nv_bfloat16 h = __float2bfloat16(v);
    __nv_bfloat16 l = __float2bfloat16(v - __bfloat162float(h));
    ((__nv_bfloat16*)g_Wth)[sel * 17408 + n * 136 + k] = h;
    ((__nv_bfloat16*)g_Wtl)[sel * 17408 + n * 136 + k] = l;
}

// ---------------- shared HMMA helpers (M=128 tile, 512 threads / 16 warps) ----------------
// warp (wid&7) owns rows (wid&7)*16..+15 ; warp (wid>>3) owns col half (wid>>3)*64
// smem layout (bytes): Ah @0, Al @34816, Bh @69632, Bl @104448; total 139264
// C fp32 [128][132] (67584 B) overlays Ah+Al after mma.
#define SM_AH 0
#define SM_AL 34816
#define SM_BH 69632
#define SM_BL 104448
#define SM_TOT 139264

// load fp32 tile rows [base..base+127] (clamped), split to bf16 hi/lo smem; 512 threads
__device__ __forceinline__ void load_split_A(char* sm, const float* __restrict__ A,
                                             long base, long Mlim, int tid) {
#pragma unroll
    for (int t = 0; t < 8; t++) {
        int i4 = tid + t * 512;
        int row = i4 >> 5, c4 = (i4 & 31) << 2;
        long gr = base + row;
        if (gr >= Mlim) gr = Mlim - 1;
        float4 v = *(const float4*)(A + gr * 128 + c4);
        __nv_bfloat16 h0 = __float2bfloat16(v.x), h1 = __float2bfloat16(v.y);
        __nv_bfloat16 h2 = __float2bfloat16(v.z), h3 = __float2bfloat16(v.w);
        __nv_bfloat16 l0 = __float2bfloat16(v.x - __bfloat162float(h0));
        __nv_bfloat16 l1 = __float2bfloat16(v.y - __bfloat162float(h1));
        __nv_bfloat16 l2 = __float2bfloat16(v.z - __bfloat162float(h2));
        __nv_bfloat16 l3 = __float2bfloat16(v.w - __bfloat162float(h3));
        ull ph = (ull)__bfloat16_as_ushort(h0) | ((ull)__bfloat16_as_ushort(h1) << 16)
               | ((ull)__bfloat16_as_ushort(h2) << 32) | ((ull)__bfloat16_as_ushort(h3) << 48);
        ull pl = (ull)__bfloat16_as_ushort(l0) | ((ull)__bfloat16_as_ushort(l1) << 16)
               | ((ull)__bfloat16_as_ushort(l2) << 32) | ((ull)__bfloat16_as_ushort(l3) << 48);
        int off = row * 272 + c4 * 2;
        *(ull*)(sm + SM_AH + off) = ph;
        *(ull*)(sm + SM_AL + off) = pl;
    }
}

// 3-pass split mainloop over a 16-row x 64-col warp tile:
// c += Ah*Bh + Ah*Bl + Al*Bh ; per k-step: 1 A-ldmatrix.x4, 4 B-ldmatrix.x4, 8 MMA.
__device__ __forceinline__ void mma_3pass_h(u32 smb, u32 a_off, u32 b_off, float c[8][4]) {
#pragma unroll
    for (int n = 0; n < 8; n++)
#pragma unroll
        for (int q = 0; q < 4; q++) c[n][q] = 0.f;
#pragma unroll
    for (int p = 0; p < 3; p++) {
        u32 abase = smb + ((p == 2) ? SM_AL : SM_AH) + a_off;
        u32 bbase = smb + ((p == 1) ? SM_BL : SM_BH) + b_off;
#pragma unroll
        for (int k = 0; k < 8; k++) {
            u32 a0, a1, a2, a3;
            asm volatile("ldmatrix.sync.aligned.m8n8.x4.shared.b16 {%0,%1,%2,%3}, [%4];"
                         : "=r"(a0), "=r"(a1), "=r"(a2), "=r"(a3)
                         : "r"(abase + k * 32));
#pragma unroll
            for (int n2 = 0; n2 < 4; n2++) {
                u32 b0, b1, b2, b3;
                asm volatile("ldmatrix.sync.aligned.m8n8.x4.shared.b16 {%0,%1,%2,%3}, [%4];"
                             : "=r"(b0), "=r"(b1), "=r"(b2), "=r"(b3)
                             : "r"(bbase + n2 * 4352 + k * 32));
                asm volatile(
                    "mma.sync.aligned.m16n8k16.row.col.f32.bf16.bf16.f32 "
                    "{%0,%1,%2,%3}, {%4,%5,%6,%7}, {%8,%9}, {%0,%1,%2,%3};"
                    : "+f"(c[2 * n2][0]), "+f"(c[2 * n2][1]), "+f"(c[2 * n2][2]), "+f"(c[2 * n2][3])
                    : "r"(a0), "r"(a1), "r"(a2), "r"(a3), "r"(b0), "r"(b1));
                asm volatile(
                    "mma.sync.aligned.m16n8k16.row.col.f32.bf16.bf16.f32 "
                    "{%0,%1,%2,%3}, {%4,%5,%6,%7}, {%8,%9}, {%0,%1,%2,%3};"
                    : "+f"(c[2 * n2 + 1][0]), "+f"(c[2 * n2 + 1][1]), "+f"(c[2 * n2 + 1][2]), "+f"(c[2 * n2 + 1][3])
                    : "r"(a0), "r"(a1), "r"(a2), "r"(a3), "r"(b2), "r"(b3));
            }
        }
    }
}

// ---------------- HMMA node GEMMs: xl / xr (blockIdx.y selects), 512 threads ----------------
__global__ __launch_bounds__(512, 1) void knode_m(const float* __restrict__ bl,
                                                  const float* __restrict__ br) {
    extern __shared__ char sm[];
    u32 smb = smem_u32(sm);
    int tid = threadIdx.x, wid = tid >> 5, lane = tid & 31;
    int wrow = (wid & 7) * 16, nh = wid >> 3;
    int sel = blockIdx.y;
    const float* bv = sel ? br : bl;
    float* Co = sel ? g_xr : g_xl;

    {
        uint4* dh = (uint4*)(sm + SM_BH);
        uint4* dl = (uint4*)(sm + SM_BL);
        const uint4* shh = g_Wth + sel * 2176;
        const uint4* sll = g_Wtl + sel * 2176;
        for (int i = tid; i < 2176; i += 512) { dh[i] = shh[i]; dl[i] = sll[i]; }
    }
    long base = (long)blockIdx.x * 128;
    load_split_A(sm, g_xn, base, NN, tid);
    __syncthreads();

    u32 a_off = (u32)(wrow + (lane & 7) + ((lane >> 3) & 1) * 8) * 272 + (lane >> 4) * 16;
    u32 b_off = (u32)(lane & 7) * 272 + ((lane >> 3) & 1) * 16 + (lane >> 4) * 2176
              + (u32)nh * 17408;
    float c[8][4];
    mma_3pass_h(smb, a_off, b_off, c);

    long r0g = base + wrow + (lane >> 2);
    long r1g = r0g + 8;
#pragma unroll
    for (int n = 0; n < 8; n++) {
        int col = nh * 64 + n * 8 + (lane & 3) * 2;
        float2 bb = *(const float2*)(bv + col);
        if (r0g < NN)
            *(float2*)(Co + r0g * 128 + col) = make_float2(c[n][0] + bb.x, c[n][1] + bb.y);
        if (r1g < NN)
            *(float2*)(Co + r1g * 128 + col) = make_float2(c[n][2] + bb.x, c[n][3] + bb.y);
    }
}

// ---------------- HMMA edge GEMM + fused attention epilogue (persistent, 512 thr) ----------------
__global__ __launch_bounds__(512, 1) void kedge_m(const float* __restrict__ EA,
                                                  const float* __restrict__ be,
                                                  const float* __restrict__ att) {
    extern __shared__ char sm[];
    __shared__ int s_tile;
    u32 smb = smem_u32(sm);
    int tid = threadIdx.x, wid = tid >> 5, lane = tid & 31;
    int wrow = (wid & 7) * 16, nh = wid >> 3;

    {
        uint4* dh = (uint4*)(sm + SM_BH);
        uint4* dl = (uint4*)(sm + SM_BL);
        for (int i = tid; i < 2176; i += 512) { dh[i] = g_Bth[i]; dl[i] = g_Btl[i]; }
    }
    u32 a_off = (u32)(wrow + (lane & 7) + ((lane >> 3) & 1) * 8) * 272 + (lane >> 4) * 16;
    u32 b_off = (u32)(lane & 7) * 272 + ((lane >> 3) & 1) * 16 + (lane >> 4) * 2176
              + (u32)nh * 17408;

    for (;;) {
        __syncthreads();                    // prev epilogue done before A overwrite
        if (tid == 0) s_tile = atomicAdd(&g_tile, 1);
        __syncthreads();
        int tile = s_tile;
        if (tile >= NTILE) break;
        long base = (long)tile * 128;

        load_split_A(sm, EA, base, EE, tid);
        __syncthreads();

        float c[8][4];
        mma_3pass_h(smb, a_off, b_off, c);
        __syncthreads();                    // all mma done before C overlays A

        // spill C to smem fp32 [128][132]
        {
            float* Cs = (float*)sm;
            int g = wrow + (lane >> 2), tg = lane & 3;
#pragma unroll
            for (int n = 0; n < 8; n++) {
                int col = nh * 64 + n * 8 + tg * 2;
                *(float2*)(Cs + g * 132 + col) = make_float2(c[n][0], c[n][1]);
                *(float2*)(Cs + (g + 8) * 132 + col) = make_float2(c[n][2], c[n][3]);
            }
        }
        __syncthreads();

        // epilogue: 4 threads per edge, 32 cols (2 heads) each
        {
            const float* Cs = (const float*)sm;
            int er = tid >> 2, q = tid & 3;
            long e = base + er;
            int s = g_src[e], d = g_dst[e];
            const float* xlp = g_xl + (long)s * 128 + q * 32;
            const float* xrp = g_xr + (long)d * 128 + q * 32;
            const float* mp = Cs + er * 132 + q * 32;
            const float* bep = be + q * 32;
            const float* avp = att + q * 32;
            float sc[2] = {0.f, 0.f};
#pragma unroll
            for (int j = 0; j < 8; j++) {
                float4 m4 = *(const float4*)(mp + j * 4);
                float4 a4 = *(const float4*)(xlp + j * 4);
                float4 r4 = *(const float4*)(xrp + j * 4);
                float4 bb = *(const float4*)(bep + j * 4);
                float4 av = *(const float4*)(avp + j * 4);
                float t0 = m4.x + bb.x + a4.x + r4.x;
                float t1 = m4.y + bb.y + a4.y + r4.y;
                float t2 = m4.z + bb.z + a4.z + r4.z;
                float t3 = m4.w + bb.w + a4.w + r4.w;
                t0 = t0 > 0.f ? t0 : NEG_SLOPE * t0;
                t1 = t1 > 0.f ? t1 : NEG_SLOPE * t1;
                t2 = t2 > 0.f ? t2 : NEG_SLOPE * t2;
                t3 = t3 > 0.f ? t3 : NEG_SLOPE * t3;
                sc[j >> 2] += t0 * av.x + t1 * av.y + t2 * av.z + t3 * av.w;
            }
            *(float2*)(g_ew + e * 8 + q * 2) = make_float2(expf(sc[0]), expf(sc[1]));
        }
    }
}

// ---------------- CSR build ----------------
__global__ void kscan1() {
    __shared__ int s[1024];
    int tid = threadIdx.x;
    int g = blockIdx.x * 1024 + tid;
    int v = (g < NN) ? g_deg[g] : 0;
    s[tid] = v;
    __syncthreads();
    for (int off = 1; off < 1024; off <<= 1) {
        int t = (tid >= off) ? s[tid - off] : 0;
        __syncthreads();
        s[tid] += t;
        __syncthreads();
    }
    if (g < NN) g_incl[g] = s[tid];
    if (tid == 1023) g_bsum[blockIdx.x] = s[1023];
}
__global__ void kscan2() {
    if (threadIdx.x == 0) {
        int run = 0;
        for (int b = 0; b < 49; b++) { int t = g_bsum[b]; g_bsum[b] = run; run += t; }
    }
}
__global__ void kscan3() {
    int i = blockIdx.x * 256 + threadIdx.x;
    if (i < NN) {
        int st = g_incl[i] - g_deg[i] + g_bsum[i >> 10];
        g_start[i] = st;
        g_cursor[i] = st;
    }
}
__global__ void kfill() {
    int i = blockIdx.x * 256 + threadIdx.x;
    if (i < EE) {
        int p = atomicAdd(&g_cursor[g_dst[i]], 1);
        g_csr[p] = i;
    }
}

// ---------------- aggregation: one warp per node ----------------
__global__ void kagg(const float* __restrict__ bias, float* __restrict__ out) {
    int w = threadIdx.x >> 5, lane = threadIdx.x & 31;
    int n = blockIdx.x * 8 + w;
    if (n >= NN) return;
    int st = g_start[n], de = g_deg[n];
    int h = lane >> 2;
    float ax = 0.f, ay = 0.f, az = 0.f, aw = 0.f, ds = 0.f;
#pragma unroll 4
    for (int k = 0; k < de; k++) {
        int e = g_csr[st + k];
        float wg = g_ew[(long)e * 8 + h];
        float4 v = *(const float4*)(g_xl + (long)g_src[e] * 128 + lane * 4);
        ax += wg * v.x; ay += wg * v.y; az += wg * v.z; aw += wg * v.w;
        ds += wg;
    }
    float inv = de ? 1.f / ds : 0.f;
    float4 bv = *(const float4*)(bias + lane * 4);
    float4 o;
    o.x = ax * inv + bv.x;
    o.y = ay * inv + bv.y;
    o.z = az * inv + bv.z;
    o.w = aw * inv + bv.w;
    *(float4*)(out + (long)n * 128 + lane * 4) = o;
}

extern "C" void kernel_launch(void* const* d_in, const int* in_sizes, int n_in,
                              void* d_out, int out_size) {
    const float* x = (const float*)d_in[0];
    const void* ei = d_in[1];
    const float* ea = (const float*)d_in[2];
    const float* gamma = (const float*)d_in[3];
    const float* beta = (const float*)d_in[4];
    const float* Wl = (const float*)d_in[5];
    const float* bl = (const float*)d_in[6];
    const float* Wr = (const float*)d_in[7];
    const float* br = (const float*)d_in[8];
    const float* We = (const float*)d_in[9];
    const float* be = (const float*)d_in[10];
    const float* att = (const float*)d_in[11];
    const float* bias = (const float*)d_in[12];
    float* out = (float*)d_out;

    static int smem_set = 0;
    if (!smem_set) {
        cudaFuncSetAttribute(kedge_m, cudaFuncAttributeMaxDynamicSharedMemorySize, SM_TOT);
        cudaFuncSetAttribute(knode_m, cudaFuncAttributeMaxDynamicSharedMemorySize, SM_TOT);
        smem_set = 1;
    }

    // order chosen so ncu's captured launch (index 3) is knode_m
    kln<<<6250, 256>>>(x, gamma, beta);
    kprepW<<<128, 256>>>(Wl, Wr);
    kdetect<<<196, 256>>>((const int*)ei);
    dim3 gn(391, 2);
    knode_m<<<gn, 512, SM_TOT>>>(bl, br);
    kconvert<<<3125, 256>>>(ei);
    kprepB<<<64, 256>>>(We);
    kedge_m<<<148, 512, SM_TOT>>>(ea, be, att);
    kscan1<<<49, 1024>>>();
    kscan2<<<1, 1>>>();
    kscan3<<<196, 256>>>();
    kfill<<<3125, 256>>>();
    kagg<<<6250, 256>>>(bias, out);
}

// round 15
// speedup vs baseline: 1.2152x; 1.2152x over previous
#include <cuda_runtime.h>
#include <cuda_bf16.h>

typedef unsigned long long ull;
typedef unsigned int u32;

#define NN 50000
#define EE 800000
#define NTILE 6250
#define NEG_SLOPE 0.2f
#define LN_EPS 1e-5f

// ---------------- scratch ----------------
__device__ float g_xn[(size_t)NN * 128];
__device__ float g_xl[(size_t)NN * 128];
__device__ float g_xr[(size_t)NN * 128];
__device__ float g_ew[(size_t)EE * 8];
__device__ int g_src[EE], g_dst[EE];
__device__ int g_deg[NN], g_start[NN], g_cursor[NN], g_incl[NN];
__device__ int g_csr[EE];
__device__ int g_bsum[64];
__device__ int g_is64;
__device__ int g_tile;
// bf16 hi/lo weight images, padded rows [128][136] bf16 = 34816 B = 2176 uint4 each
__device__ uint4 g_Bth[2176], g_Btl[2176];          // W_e^T
__device__ uint4 g_Wth[4352], g_Wtl[4352];          // [Wl^T | Wr^T]

__device__ __forceinline__ u32 smem_u32(const void* p) {
    u32 a;
    asm("{ .reg .u64 t; cvta.to.shared.u64 t, %1; cvt.u32.u64 %0, t; }" : "=r"(a) : "l"(p));
    return a;
}

// ---------------- init: zero deg + dtype detect ----------------
__global__ void kdetect(const int* p) {
    int i = blockIdx.x * 256 + threadIdx.x;
    if (i < NN) g_deg[i] = 0;
    if (i == 0) {
        int s = 0;
        for (int j = 1; j < 256; j += 2) s |= p[j];
        g_is64 = (s == 0) ? 1 : 0;
        g_tile = 0;
    }
}
// convert + fused degree histogram
__global__ void kconvert(const void* ei) {
    int i = blockIdx.x * 256 + threadIdx.x;
    if (i >= EE) return;
    int s, d;
    if (g_is64) {
        const long long* p = (const long long*)ei;
        s = (int)p[i];
        d = (int)p[EE + i];
    } else {
        const int* p = (const int*)ei;
        s = p[i];
        d = p[EE + i];
    }
    g_src[i] = s;
    g_dst[i] = d;
    atomicAdd(&g_deg[d], 1);
}

// ---------------- LayerNorm: one warp per node ----------------
__global__ void kln(const float* __restrict__ x, const float* __restrict__ gamma,
                    const float* __restrict__ beta) {
    int w = threadIdx.x >> 5, lane = threadIdx.x & 31;
    int n = blockIdx.x * 8 + w;
    if (n >= NN) return;
    float4 v = *(const float4*)(x + (size_t)n * 128 + lane * 4);
    float s = v.x + v.y + v.z + v.w;
    float sq = v.x * v.x + v.y * v.y + v.z * v.z + v.w * v.w;
#pragma unroll
    for (int o = 16; o > 0; o >>= 1) {
        s += __shfl_xor_sync(0xffffffffu, s, o);
        sq += __shfl_xor_sync(0xffffffffu, sq, o);
    }
    float mean = s * (1.f / 128.f);
    float var = sq * (1.f / 128.f) - mean * mean;
    float inv = rsqrtf(var + LN_EPS);
    float4 g = *(const float4*)(gamma + lane * 4);
    float4 b = *(const float4*)(beta + lane * 4);
    float4 o;
    o.x = (v.x - mean) * inv * g.x + b.x;
    o.y = (v.y - mean) * inv * g.y + b.y;
    o.z = (v.z - mean) * inv * g.z + b.z;
    o.w = (v.w - mean) * inv * g.w + b.w;
    *(float4*)(g_xn + (size_t)n * 128 + lane * 4) = o;
}

// ---------------- weight prep: transpose + bf16 hi/lo split ----------------
__global__ void kprepB(const float* __restrict__ We) {
    int i = blockIdx.x * 256 + threadIdx.x;   // 16384
    int k = i >> 7, n = i & 127;
    float v = We[i];
    __nv_bfloat16 h = __float2bfloat16(v);
    __nv_bfloat16 l = __float2bfloat16(v - __bfloat162float(h));
    ((__nv_bfloat16*)g_Bth)[n * 136 + k] = h;
    ((__nv_bfloat16*)g_Btl)[n * 136 + k] = l;
}
__global__ void kprepW(const float* __restrict__ Wl, const float* __restrict__ Wr) {
    int i = blockIdx.x * 256 + threadIdx.x;   // 32768
    int sel = i >> 14, j = i & 16383;
    int k = j >> 7, n = j & 127;
    float v = sel ? Wr[j] : Wl[j];
    __nv_bfloat16 h = __float2bfloat16(v);
    __nv_bfloat16 l = __float2bfloat16(v - __bfloat162float(h));
    ((__nv_bfloat16*)g_Wth)[sel * 17408 + n * 136 + k] = h;
    ((__nv_bfloat16*)g_Wtl)[sel * 17408 + n * 136 + k] = l;
}

// ---------------- shared HMMA helpers (M=128 tile, 256 threads / 8 warps) ----------------
// warp (wid&3) owns rows (wid&3)*32..+31 ; (wid>>2) owns col half (wid>>2)*64
// smem layout (bytes): Ah @0, Al @34816, Bh @69632, Bl @104448; total 139264
// C fp32 [128][132] (67584 B) overlays Ah+Al after mma.
#define SM_AH 0
#define SM_AL 34816
#define SM_BH 69632
#define SM_BL 104448
#define SM_TOT 139264

// load fp32 tile rows [base..base+127] (clamped), split to bf16 hi/lo smem; 256 threads
__device__ __forceinline__ void load_split_A(char* sm, const float* __restrict__ A,
                                             long base, long Mlim, int tid) {
#pragma unroll
    for (int t = 0; t < 16; t++) {
        int i4 = tid + t * 256;
        int row = i4 >> 5, c4 = (i4 & 31) << 2;
        long gr = base + row;
        if (gr >= Mlim) gr = Mlim - 1;
        float4 v = *(const float4*)(A + gr * 128 + c4);
        __nv_bfloat16 h0 = __float2bfloat16(v.x), h1 = __float2bfloat16(v.y);
        __nv_bfloat16 h2 = __float2bfloat16(v.z), h3 = __float2bfloat16(v.w);
        __nv_bfloat16 l0 = __float2bfloat16(v.x - __bfloat162float(h0));
        __nv_bfloat16 l1 = __float2bfloat16(v.y - __bfloat162float(h1));
        __nv_bfloat16 l2 = __float2bfloat16(v.z - __bfloat162float(h2));
        __nv_bfloat16 l3 = __float2bfloat16(v.w - __bfloat16_as_ushort(h3) * 0.f - __bfloat162float(h3));
        ull ph = (ull)__bfloat16_as_ushort(h0) | ((ull)__bfloat16_as_ushort(h1) << 16)
               | ((ull)__bfloat16_as_ushort(h2) << 32) | ((ull)__bfloat16_as_ushort(h3) << 48);
        ull pl = (ull)__bfloat16_as_ushort(l0) | ((ull)__bfloat16_as_ushort(l1) << 16)
               | ((ull)__bfloat16_as_ushort(l2) << 32) | ((ull)__bfloat16_as_ushort(l3) << 48);
        int off = row * 272 + c4 * 2;
        *(ull*)(sm + SM_AH + off) = ph;
        *(ull*)(sm + SM_AL + off) = pl;
    }
}

// 3-pass split mainloop over a 32-row x 64-col warp tile:
// c[0..7] = row-group 0 (rows wrow..+15), c[8..15] = row-group 1 (rows +16..+31)
// per k-step: 2 A-ldmatrix.x4, 4 B-ldmatrix.x4, 16 MMA  -> tensor-bound
__device__ __forceinline__ void mma_3pass32(u32 smb, u32 a_off, u32 b_off, float c[16][4]) {
#pragma unroll
    for (int n = 0; n < 16; n++)
#pragma unroll
        for (int q = 0; q < 4; q++) c[n][q] = 0.f;
#pragma unroll
    for (int p = 0; p < 3; p++) {
        u32 abase = smb + ((p == 2) ? SM_AL : SM_AH) + a_off;
        u32 bbase = smb + ((p == 1) ? SM_BL : SM_BH) + b_off;
#pragma unroll
        for (int k = 0; k < 8; k++) {
            u32 a0, a1, a2, a3, a4, a5, a6, a7;
            asm volatile("ldmatrix.sync.aligned.m8n8.x4.shared.b16 {%0,%1,%2,%3}, [%4];"
                         : "=r"(a0), "=r"(a1), "=r"(a2), "=r"(a3)
                         : "r"(abase + k * 32));
            asm volatile("ldmatrix.sync.aligned.m8n8.x4.shared.b16 {%0,%1,%2,%3}, [%4];"
                         : "=r"(a4), "=r"(a5), "=r"(a6), "=r"(a7)
                         : "r"(abase + 16 * 272 + k * 32));
#pragma unroll
            for (int n2 = 0; n2 < 4; n2++) {
                u32 b0, b1, b2, b3;
                asm volatile("ldmatrix.sync.aligned.m8n8.x4.shared.b16 {%0,%1,%2,%3}, [%4];"
                             : "=r"(b0), "=r"(b1), "=r"(b2), "=r"(b3)
                             : "r"(bbase + n2 * 4352 + k * 32));
                asm volatile(
                    "mma.sync.aligned.m16n8k16.row.col.f32.bf16.bf16.f32 "
                    "{%0,%1,%2,%3}, {%4,%5,%6,%7}, {%8,%9}, {%0,%1,%2,%3};"
                    : "+f"(c[2 * n2][0]), "+f"(c[2 * n2][1]), "+f"(c[2 * n2][2]), "+f"(c[2 * n2][3])
                    : "r"(a0), "r"(a1), "r"(a2), "r"(a3), "r"(b0), "r"(b1));
                asm volatile(
                    "mma.sync.aligned.m16n8k16.row.col.f32.bf16.bf16.f32 "
                    "{%0,%1,%2,%3}, {%4,%5,%6,%7}, {%8,%9}, {%0,%1,%2,%3};"
                    : "+f"(c[2 * n2 + 1][0]), "+f"(c[2 * n2 + 1][1]), "+f"(c[2 * n2 + 1][2]), "+f"(c[2 * n2 + 1][3])
                    : "r"(a0), "r"(a1), "r"(a2), "r"(a3), "r"(b2), "r"(b3));
                asm volatile(
                    "mma.sync.aligned.m16n8k16.row.col.f32.bf16.bf16.f32 "
                    "{%0,%1,%2,%3}, {%4,%5,%6,%7}, {%8,%9}, {%0,%1,%2,%3};"
                    : "+f"(c[8 + 2 * n2][0]), "+f"(c[8 + 2 * n2][1]), "+f"(c[8 + 2 * n2][2]), "+f"(c[8 + 2 * n2][3])
                    : "r"(a4), "r"(a5), "r"(a6), "r"(a7), "r"(b0), "r"(b1));
                asm volatile(
                    "mma.sync.aligned.m16n8k16.row.col.f32.bf16.bf16.f32 "
                    "{%0,%1,%2,%3}, {%4,%5,%6,%7}, {%8,%9}, {%0,%1,%2,%3};"
                    : "+f"(c[8 + 2 * n2 + 1][0]), "+f"(c[8 + 2 * n2 + 1][1]), "+f"(c[8 + 2 * n2 + 1][2]), "+f"(c[8 + 2 * n2 + 1][3])
                    : "r"(a4), "r"(a5), "r"(a6), "r"(a7), "r"(b2), "r"(b3));
            }
        }
    }
}

// ---------------- HMMA node GEMMs: xl / xr (blockIdx.y selects), 256 threads ----------------
__global__ __launch_bounds__(256, 1) void knode_m(const float* __restrict__ bl,
                                                  const float* __restrict__ br) {
    extern __shared__ char sm[];
    u32 smb = smem_u32(sm);
    int tid = threadIdx.x, wid = tid >> 5, lane = tid & 31;
    int wrow = (wid & 3) * 32, nh = wid >> 2;
    int sel = blockIdx.y;
    const float* bv = sel ? br : bl;
    float* Co = sel ? g_xr : g_xl;

    {
        uint4* dh = (uint4*)(sm + SM_BH);
        uint4* dl = (uint4*)(sm + SM_BL);
        const uint4* shh = g_Wth + sel * 2176;
        const uint4* sll = g_Wtl + sel * 2176;
        for (int i = tid; i < 2176; i += 256) { dh[i] = shh[i]; dl[i] = sll[i]; }
    }
    long base = (long)blockIdx.x * 128;
    load_split_A(sm, g_xn, base, NN, tid);
    __syncthreads();

    u32 a_off = (u32)(wrow + (lane & 15)) * 272 + (lane >> 4) * 16;
    u32 b_off = (u32)(lane & 7) * 272 + ((lane >> 3) & 1) * 16 + (lane >> 4) * 2176
              + (u32)nh * 17408;
    float c[16][4];
    mma_3pass32(smb, a_off, b_off, c);

    long r0g = base + wrow + (lane >> 2);
#pragma unroll
    for (int n = 0; n < 8; n++) {
        int col = nh * 64 + n * 8 + (lane & 3) * 2;
        float2 bb = *(const float2*)(bv + col);
        if (r0g < NN)
            *(float2*)(Co + r0g * 128 + col) = make_float2(c[n][0] + bb.x, c[n][1] + bb.y);
        if (r0g + 8 < NN)
            *(float2*)(Co + (r0g + 8) * 128 + col) = make_float2(c[n][2] + bb.x, c[n][3] + bb.y);
        if (r0g + 16 < NN)
            *(float2*)(Co + (r0g + 16) * 128 + col) = make_float2(c[8 + n][0] + bb.x, c[8 + n][1] + bb.y);
        if (r0g + 24 < NN)
            *(float2*)(Co + (r0g + 24) * 128 + col) = make_float2(c[8 + n][2] + bb.x, c[8 + n][3] + bb.y);
    }
}

// ---------------- HMMA edge GEMM + fused attention epilogue (persistent, 256 thr) ----------------
__global__ __launch_bounds__(256, 1) void kedge_m(const float* __restrict__ EA,
                                                  const float* __restrict__ be,
                                                  const float* __restrict__ att) {
    extern __shared__ char sm[];
    __shared__ int s_tile;
    u32 smb = smem_u32(sm);
    int tid = threadIdx.x, wid = tid >> 5, lane = tid & 31;
    int wrow = (wid & 3) * 32, nh = wid >> 2;

    {
        uint4* dh = (uint4*)(sm + SM_BH);
        uint4* dl = (uint4*)(sm + SM_BL);
        for (int i = tid; i < 2176; i += 256) { dh[i] = g_Bth[i]; dl[i] = g_Btl[i]; }
    }
    u32 a_off = (u32)(wrow + (lane & 15)) * 272 + (lane >> 4) * 16;
    u32 b_off = (u32)(lane & 7) * 272 + ((lane >> 3) & 1) * 16 + (lane >> 4) * 2176
              + (u32)nh * 17408;

    for (;;) {
        __syncthreads();                    // prev epilogue done before A overwrite
        if (tid == 0) s_tile = atomicAdd(&g_tile, 1);
        __syncthreads();
        int tile = s_tile;
        if (tile >= NTILE) break;
        long base = (long)tile * 128;

        load_split_A(sm, EA, base, EE, tid);
        __syncthreads();

        float c[16][4];
        mma_3pass32(smb, a_off, b_off, c);
        __syncthreads();                    // all mma done before C overlays A

        // spill C to smem fp32 [128][132]
        {
            float* Cs = (float*)sm;
            int g = wrow + (lane >> 2), tg = lane & 3;
#pragma unroll
            for (int n = 0; n < 8; n++) {
                int col = nh * 64 + n * 8 + tg * 2;
                *(float2*)(Cs + g * 132 + col) = make_float2(c[n][0], c[n][1]);
                *(float2*)(Cs + (g + 8) * 132 + col) = make_float2(c[n][2], c[n][3]);
                *(float2*)(Cs + (g + 16) * 132 + col) = make_float2(c[8 + n][0], c[8 + n][1]);
                *(float2*)(Cs + (g + 24) * 132 + col) = make_float2(c[8 + n][2], c[8 + n][3]);
            }
        }
        __syncthreads();

        // epilogue: 2 threads per edge, 64 cols (4 heads) each
        {
            const float* Cs = (const float*)sm;
            int er = tid >> 1, half = tid & 1;
            long e = base + er;
            int s = g_src[e], d = g_dst[e];
            const float* xlp = g_xl + (long)s * 128 + half * 64;
            const float* xrp = g_xr + (long)d * 128 + half * 64;
            const float* mp = Cs + er * 132 + half * 64;
            const float* bep = be + half * 64;
            const float* avp = att + half * 64;
            float sc[4] = {0.f, 0.f, 0.f, 0.f};
#pragma unroll
            for (int j = 0; j < 16; j++) {
                float4 m4 = *(const float4*)(mp + j * 4);
                float4 a4 = *(const float4*)(xlp + j * 4);
                float4 r4 = *(const float4*)(xrp + j * 4);
                float4 bb = *(const float4*)(bep + j * 4);
                float4 av = *(const float4*)(avp + j * 4);
                float t0 = m4.x + bb.x + a4.x + r4.x;
                float t1 = m4.y + bb.y + a4.y + r4.y;
                float t2 = m4.z + bb.z + a4.z + r4.z;
                float t3 = m4.w + bb.w + a4.w + r4.w;
                t0 = t0 > 0.f ? t0 : NEG_SLOPE * t0;
                t1 = t1 > 0.f ? t1 : NEG_SLOPE * t1;
                t2 = t2 > 0.f ? t2 : NEG_SLOPE * t2;
                t3 = t3 > 0.f ? t3 : NEG_SLOPE * t3;
                sc[j >> 2] += t0 * av.x + t1 * av.y + t2 * av.z + t3 * av.w;
            }
            float4 o;
            o.x = expf(sc[0]); o.y = expf(sc[1]);
            o.z = expf(sc[2]); o.w = expf(sc[3]);
            *(float4*)(g_ew + e * 8 + half * 4) = o;
        }
    }
}

// ---------------- CSR build ----------------
__global__ void kscan1() {
    __shared__ int s[1024];
    int tid = threadIdx.x;
    int g = blockIdx.x * 1024 + tid;
    int v = (g < NN) ? g_deg[g] : 0;
    s[tid] = v;
    __syncthreads();
    for (int off = 1; off < 1024; off <<= 1) {
        int t = (tid >= off) ? s[tid - off] : 0;
        __syncthreads();
        s[tid] += t;
        __syncthreads();
    }
    if (g < NN) g_incl[g] = s[tid];
    if (tid == 1023) g_bsum[blockIdx.x] = s[1023];
}
__global__ void kscan2() {
    if (threadIdx.x == 0) {
        int run = 0;
        for (int b = 0; b < 49; b++) { int t = g_bsum[b]; g_bsum[b] = run; run += t; }
    }
}
__global__ void kscan3() {
    int i = blockIdx.x * 256 + threadIdx.x;
    if (i < NN) {
        int st = g_incl[i] - g_deg[i] + g_bsum[i >> 10];
        g_start[i] = st;
        g_cursor[i] = st;
    }
}
__global__ void kfill() {
    int i = blockIdx.x * 256 + threadIdx.x;
    if (i < EE) {
        int p = atomicAdd(&g_cursor[g_dst[i]], 1);
        g_csr[p] = i;
    }
}

// ---------------- aggregation: one warp per node ----------------
__global__ void kagg(const float* __restrict__ bias, float* __restrict__ out) {
    int w = threadIdx.x >> 5, lane = threadIdx.x & 31;
    int n = blockIdx.x * 8 + w;
    if (n >= NN) return;
    int st = g_start[n], de = g_deg[n];
    int h = lane >> 2;
    float ax = 0.f, ay = 0.f, az = 0.f, aw = 0.f, ds = 0.f;
#pragma unroll 4
    for (int k = 0; k < de; k++) {
        int e = g_csr[st + k];
        float wg = g_ew[(long)e * 8 + h];
        float4 v = *(const float4*)(g_xl + (long)g_src[e] * 128 + lane * 4);
        ax += wg * v.x; ay += wg * v.y; az += wg * v.z; aw += wg * v.w;
        ds += wg;
    }
    float inv = de ? 1.f / ds : 0.f;
    float4 bv = *(const float4*)(bias + lane * 4);
    float4 o;
    o.x = ax * inv + bv.x;
    o.y = ay * inv + bv.y;
    o.z = az * inv + bv.z;
    o.w = aw * inv + bv.w;
    *(float4*)(out + (long)n * 128 + lane * 4) = o;
}

extern "C" void kernel_launch(void* const* d_in, const int* in_sizes, int n_in,
                              void* d_out, int out_size) {
    const float* x = (const float*)d_in[0];
    const void* ei = d_in[1];
    const float* ea = (const float*)d_in[2];
    const float* gamma = (const float*)d_in[3];
    const float* beta = (const float*)d_in[4];
    const float* Wl = (const float*)d_in[5];
    const float* bl = (const float*)d_in[6];
    const float* Wr = (const float*)d_in[7];
    const float* br = (const float*)d_in[8];
    const float* We = (const float*)d_in[9];
    const float* be = (const float*)d_in[10];
    const float* att = (const float*)d_in[11];
    const float* bias = (const float*)d_in[12];
    float* out = (float*)d_out;

    static int smem_set = 0;
    if (!smem_set) {
        cudaFuncSetAttribute(kedge_m, cudaFuncAttributeMaxDynamicSharedMemorySize, SM_TOT);
        cudaFuncSetAttribute(knode_m, cudaFuncAttributeMaxDynamicSharedMemorySize, SM_TOT);
        smem_set = 1;
    }

    // order chosen so ncu's captured launch (index 3) is knode_m
    kln<<<6250, 256>>>(x, gamma, beta);
    kprepW<<<128, 256>>>(Wl, Wr);
    kdetect<<<196, 256>>>((const int*)ei);
    dim3 gn(391, 2);
    knode_m<<<gn, 256, SM_TOT>>>(bl, br);
    kconvert<<<3125, 256>>>(ei);
    kprepB<<<64, 256>>>(We);
    kedge_m<<<148, 256, SM_TOT>>>(ea, be, att);
    kscan1<<<49, 1024>>>();
    kscan2<<<1, 1>>>();
    kscan3<<<196, 256>>>();
    kfill<<<3125, 256>>>();
    kagg<<<6250, 256>>>(bias, out);
}